// round 7
// baseline (speedup 1.0000x reference)
#include <cuda_runtime.h>
#include <cstdint>

// Problem constants (match reference)
#define N_EVENTS   16
#define N_SAMPLES  32768
#define STEP_SIZE  256
#define BATCH      64

// out[b,j] = sum_e (j >= 256*idx[b,e]) ? x[b,e, j - 256*idx[b,e]] : 0
// Pure gather (race-free, each covered input element read exactly once):
// ~67.6 MB compulsory reads + 8.4 MB writes -> HBM-bound floor (~7 TB/s achieved).
//
// Each thread produces 4 consecutive output samples (float4).
// 256 threads/block -> 1024 samples per block -> 32 blocks per batch row.
// Per event each CTA reads ONE contiguous 4KB region -> clean DRAM streams.
// Indices loaded directly per-thread (uniform within warp -> L1 broadcast).
//
// __launch_bounds__(256, 4): allow up to 64 regs/thread so ptxas can
// front-batch more of the 16 float4 loads per thread (higher MLP_p1);
// 4 CTAs/SM = 32 warps/SM is still ample latency-hiding for a DRAM-bound
// kernel.
#define THREADS    256
#define SAMPLES_PER_BLOCK (THREADS * 4)

__global__ __launch_bounds__(THREADS, 4)
void render_gather_kernel(const float* __restrict__ x,
                          const int* __restrict__ indices,
                          float* __restrict__ out) {
    const int b = blockIdx.y;
    const int j = (blockIdx.x * THREADS + threadIdx.x) * 4;  // output sample base

    const int* idx_b = indices + b * N_EVENTS;
    const float* xb = x + (size_t)b * N_EVENTS * N_SAMPLES;

    // Load all 16 start times up front (independent scalar loads).
    int t[N_EVENTS];
    #pragma unroll
    for (int e = 0; e < N_EVENTS; e++) {
        t[e] = __ldg(idx_b + e) * STEP_SIZE;   // uniform across warp
    }

    // Issue all predicated float4 loads, then reduce.
    float4 v[N_EVENTS];
    #pragma unroll
    for (int e = 0; e < N_EVENTS; e++) {
        const int k = j - t[e];
        // t multiple of 256, j multiple of 4 -> k multiple of 4 (16B aligned).
        // k < N_SAMPLES always holds since j < N_SAMPLES and t >= 0.
        v[e] = (k >= 0)
             ? *reinterpret_cast<const float4*>(xb + (size_t)e * N_SAMPLES + k)
             : make_float4(0.f, 0.f, 0.f, 0.f);
    }

    float4 acc = make_float4(0.f, 0.f, 0.f, 0.f);
    #pragma unroll
    for (int e = 0; e < N_EVENTS; e++) {
        acc.x += v[e].x; acc.y += v[e].y; acc.z += v[e].z; acc.w += v[e].w;
    }

    *reinterpret_cast<float4*>(out + (size_t)b * N_SAMPLES + j) = acc;
}

extern "C" void kernel_launch(void* const* d_in, const int* in_sizes, int n_in,
                              void* d_out, int out_size) {
    const float* x = (const float*)d_in[0];          // (64, 16, 32768) f32
    const int* indices = (const int*)d_in[1];        // (64, 16) int32
    float* out = (float*)d_out;                      // (64, 1, 32768) f32

    dim3 grid(N_SAMPLES / SAMPLES_PER_BLOCK, BATCH); // (32, 64) = 2048 CTAs
    render_gather_kernel<<<grid, THREADS>>>(x, indices, out);
}